// round 1
// baseline (speedup 1.0000x reference)
#include <cuda_runtime.h>
#include <math.h>

#define BB 8
#define SS 200
#define HH 4
#define DD 64
#define HID 256
#define NBS (BB*SS)   // 1600

// scratch (device globals; no allocation allowed)
__device__ float g_q[NBS*HID];
__device__ float g_kpos[NBS*HID];
__device__ float g_vpos[NBS*HID];
__device__ float g_qo[BB*HH*SS];
__device__ float g_ko[BB*HH*SS];
__device__ float g_qd[BB*HH*SS];
__device__ float g_kd[BB*HH*SS];
__device__ float g_ctx[NBS*HID];

// ---------------------------------------------------------------------------
// Kernel 1: fused QKV projection (M=8 rows/block) + kpos/vpos + order/dist dots
// ---------------------------------------------------------------------------
__global__ __launch_bounds__(256) void qkv_kernel(
    const float* __restrict__ x,
    const float* __restrict__ posK, const float* __restrict__ posV,
    const float* __restrict__ Wq, const float* __restrict__ bq,
    const float* __restrict__ Wk, const float* __restrict__ bk,
    const float* __restrict__ Wv, const float* __restrict__ bv,
    const float* __restrict__ order_w, const float* __restrict__ dist_w)
{
    const int f  = threadIdx.x;
    const int r0 = blockIdx.x * 8;

    __shared__ float xs[8][HID];
    __shared__ float qs[8][HID];
    __shared__ float ks[8][HID];

    #pragma unroll
    for (int m = 0; m < 8; m++) xs[m][f] = x[(r0 + m) * HID + f];
    __syncthreads();

    float aq[8], ak[8], av[8];
    const float vbq = bq[f], vbk = bk[f], vbv = bv[f];
    #pragma unroll
    for (int m = 0; m < 8; m++) { aq[m] = vbq; ak[m] = vbk; av[m] = vbv; }

    for (int g = 0; g < HID; g++) {
        const float wq = Wq[g * HID + f];
        const float wk = Wk[g * HID + f];
        const float wv = Wv[g * HID + f];
        #pragma unroll
        for (int m = 0; m < 8; m++) {
            const float xv = xs[m][g];
            aq[m] += xv * wq;
            ak[m] += xv * wk;
            av[m] += xv * wv;
        }
    }

    #pragma unroll
    for (int m = 0; m < 8; m++) {
        const int row = r0 + m;
        g_q[row * HID + f]    = aq[m];
        qs[m][f]              = aq[m];
        ks[m][f]              = ak[m];
        g_kpos[row * HID + f] = ak[m] + posK[row * HID + f];
        g_vpos[row * HID + f] = av[m] + posV[row * HID + f];
    }
    __syncthreads();

    // order/dist scalar dots: warp m reduces row r0+m
    const int w = f >> 5, l = f & 31;
    const int row = r0 + w;
    const int b = row / SS, s = row % SS;
    #pragma unroll
    for (int h = 0; h < HH; h++) {
        float qo = qs[w][h*64 + l] * order_w[l]      + qs[w][h*64 + 32 + l] * order_w[32 + l];
        float qd = qs[w][h*64 + l] * dist_w[l]       + qs[w][h*64 + 32 + l] * dist_w[32 + l];
        float ko = ks[w][h*64 + l] * order_w[64 + l] + ks[w][h*64 + 32 + l] * order_w[96 + l];
        float kd = ks[w][h*64 + l] * dist_w[64 + l]  + ks[w][h*64 + 32 + l] * dist_w[96 + l];
        #pragma unroll
        for (int off = 16; off; off >>= 1) {
            qo += __shfl_xor_sync(0xffffffffu, qo, off);
            qd += __shfl_xor_sync(0xffffffffu, qd, off);
            ko += __shfl_xor_sync(0xffffffffu, ko, off);
            kd += __shfl_xor_sync(0xffffffffu, kd, off);
        }
        if (l == 0) {
            const int idx = (b * HH + h) * SS + s;
            g_qo[idx] = qo; g_qd[idx] = qd; g_ko[idx] = ko; g_kd[idx] = kd;
        }
    }
}

// ---------------------------------------------------------------------------
// Kernel 2: per-(b,i) attention: scores (timeK stream) -> softmax -> ctx
// (timeV stream). One block per (b,i), 256 threads.
// ---------------------------------------------------------------------------
__global__ __launch_bounds__(256) void attn_kernel(
    const float* __restrict__ timeK, const float* __restrict__ timeV,
    const float* __restrict__ mask,
    const float* __restrict__ p_order_b, const float* __restrict__ p_dist_b,
    const float* __restrict__ p_scalar)
{
    const int tid = threadIdx.x;
    const int blk = blockIdx.x;
    const int b = blk / SS, i = blk % SS;
    const int w = tid >> 5, l = tid & 31;

    __shared__ float sc[HH][SS];    // scores, then un-normalized probs
    __shared__ float qos[HH], qds[HH];
    __shared__ float inv_s[HH];
    __shared__ float q_sh[HID];

    q_sh[tid] = g_q[(b * SS + i) * HID + tid];
    if (tid < HH) {
        qos[tid] = g_qo[(b * HH + tid) * SS + i];
        qds[tid] = g_qd[(b * HH + tid) * SS + i];
    }
    __syncthreads();

    // per-lane fixed q slice: floats [8l, 8l+8)
    const float4 q0 = *(const float4*)&q_sh[l * 8];
    const float4 q1 = *(const float4*)&q_sh[l * 8 + 4];
    const int hh = l >> 3;  // head owned by this 8-lane group

    // ---- phase 1: raw scores  q . (timeK_ij + k_j + posK_j) ----
    const float* tkb = timeK + ((size_t)(b * SS + i)) * SS * HID;
    for (int j = w; j < SS; j += 8) {
        const float4* tk = (const float4*)(tkb + (size_t)j * HID);
        const float4* kp = (const float4*)(g_kpos + (size_t)(b * SS + j) * HID);
        const float4 t0 = tk[2 * l],     t1 = tk[2 * l + 1];
        const float4 k0 = kp[2 * l],     k1 = kp[2 * l + 1];
        float p = q0.x * (t0.x + k0.x) + q0.y * (t0.y + k0.y)
                + q0.z * (t0.z + k0.z) + q0.w * (t0.w + k0.w)
                + q1.x * (t1.x + k1.x) + q1.y * (t1.y + k1.y)
                + q1.z * (t1.z + k1.z) + q1.w * (t1.w + k1.w);
        p += __shfl_xor_sync(0xffffffffu, p, 1);
        p += __shfl_xor_sync(0xffffffffu, p, 2);
        p += __shfl_xor_sync(0xffffffffu, p, 4);
        if ((l & 7) == 0) sc[hh][j] = p;
    }
    __syncthreads();

    // ---- phase 2: order/dist error terms, scale, mask ----
    const float order_b = *p_order_b;
    const float dist_b  = *p_dist_b;
    const float sc2 = p_scalar[0] * p_scalar[0] * 0.5f;
    for (int idx = tid; idx < HH * SS; idx += 256) {
        const int h = idx / SS, j = idx % SS;
        const float pr = 1.f / (1.f + expf(-(qos[h] + g_ko[(b * HH + h) * SS + j] + order_b)));
        const float eo = (j > i) ? logf(pr + 1e-24f) : logf(1.f - pr + 1e-24f);
        const float gd = logf(fabsf((float)(j - i)) + 1.f);
        const float pd = qds[h] + g_kd[(b * HH + h) * SS + j] + dist_b;
        const float ed = -(gd - pd) * (gd - pd) * sc2;
        sc[h][j] = (sc[h][j] + eo + ed) * 0.125f
                 + mask[((size_t)b * SS + i) * SS + j];
    }
    __syncthreads();

    // ---- phase 3: softmax (warp h handles head h); store exp, keep 1/sum ----
    if (w < HH) {
        float m = -1e30f;
        for (int j = l; j < SS; j += 32) m = fmaxf(m, sc[w][j]);
        #pragma unroll
        for (int off = 16; off; off >>= 1)
            m = fmaxf(m, __shfl_xor_sync(0xffffffffu, m, off));
        float sum = 0.f;
        for (int j = l; j < SS; j += 32) {
            const float e = expf(sc[w][j] - m);
            sc[w][j] = e;
            sum += e;
        }
        #pragma unroll
        for (int off = 16; off; off >>= 1)
            sum += __shfl_xor_sync(0xffffffffu, sum, off);
        if (l == 0) inv_s[w] = 1.f / sum;
    }
    __syncthreads();

    // ---- phase 4: ctx[f] = (1/sum_h) * sum_j e[h][j]*(timeV_ij[f] + v_j[f] + posV_j[f])
    const int f = tid;
    const int h = f >> 6;
    const float* tvb = timeV + ((size_t)(b * SS + i)) * SS * HID + f;
    const float* vp  = g_vpos + (size_t)b * SS * HID + f;
    float acc = 0.f;
    #pragma unroll 4
    for (int j = 0; j < SS; j++)
        acc += sc[h][j] * (tvb[(size_t)j * HID] + vp[(size_t)j * HID]);
    g_ctx[((size_t)b * SS + i) * HID + f] = acc * inv_s[h];
}

// ---------------------------------------------------------------------------
// Kernel 3: output projection (M=8 rows/block) + residual + LayerNorm
// ---------------------------------------------------------------------------
__global__ __launch_bounds__(256) void outln_kernel(
    const float* __restrict__ x,
    const float* __restrict__ Wd, const float* __restrict__ bd,
    const float* __restrict__ ln_g, const float* __restrict__ ln_b,
    float* __restrict__ out)
{
    const int f  = threadIdx.x;
    const int r0 = blockIdx.x * 8;

    __shared__ float cs[8][HID];
    __shared__ float hsm[8][HID];
    __shared__ float mu[8], rstd[8];

    #pragma unroll
    for (int m = 0; m < 8; m++) cs[m][f] = g_ctx[(r0 + m) * HID + f];
    __syncthreads();

    float acc[8];
    const float bdf = bd[f];
    #pragma unroll
    for (int m = 0; m < 8; m++) acc[m] = bdf;

    for (int g = 0; g < HID; g++) {
        const float wv = Wd[g * HID + f];
        #pragma unroll
        for (int m = 0; m < 8; m++) acc[m] += cs[m][g] * wv;
    }

    #pragma unroll
    for (int m = 0; m < 8; m++)
        hsm[m][f] = acc[m] + x[(r0 + m) * HID + f];
    __syncthreads();

    const int w = f >> 5, l = f & 31;
    float s = 0.f, s2 = 0.f;
    #pragma unroll
    for (int t = 0; t < 8; t++) {
        const float v = hsm[w][l + 32 * t];
        s += v; s2 += v * v;
    }
    #pragma unroll
    for (int off = 16; off; off >>= 1) {
        s  += __shfl_xor_sync(0xffffffffu, s,  off);
        s2 += __shfl_xor_sync(0xffffffffu, s2, off);
    }
    if (l == 0) {
        const float m_  = s / HID;
        const float var = s2 / HID - m_ * m_;
        mu[w]   = m_;
        rstd[w] = rsqrtf(var + 1e-12f);
    }
    __syncthreads();

    const float gf = ln_g[f], bf = ln_b[f];
    #pragma unroll
    for (int m = 0; m < 8; m++)
        out[(r0 + m) * HID + f] = (hsm[m][f] - mu[m]) * rstd[m] * gf + bf;
}

// ---------------------------------------------------------------------------
extern "C" void kernel_launch(void* const* d_in, const int* in_sizes, int n_in,
                              void* d_out, int out_size)
{
    const float* x     = (const float*)d_in[0];
    const float* mask  = (const float*)d_in[1];
    const float* posK  = (const float*)d_in[2];
    const float* posV  = (const float*)d_in[3];
    const float* timeK = (const float*)d_in[4];
    const float* timeV = (const float*)d_in[5];
    const float* Wq = (const float*)d_in[6];  const float* bq = (const float*)d_in[7];
    const float* Wk = (const float*)d_in[8];  const float* bk = (const float*)d_in[9];
    const float* Wv = (const float*)d_in[10]; const float* bv = (const float*)d_in[11];
    const float* ow = (const float*)d_in[12]; const float* ob = (const float*)d_in[13];
    const float* dw = (const float*)d_in[14]; const float* db = (const float*)d_in[15];
    const float* sca = (const float*)d_in[16];
    const float* Wd = (const float*)d_in[17]; const float* bd = (const float*)d_in[18];
    const float* lg = (const float*)d_in[19]; const float* lb = (const float*)d_in[20];

    qkv_kernel<<<NBS / 8, 256>>>(x, posK, posV, Wq, bq, Wk, bk, Wv, bv, ow, dw);
    attn_kernel<<<NBS, 256>>>(timeK, timeV, mask, ob, db, sca);
    outln_kernel<<<NBS / 8, 256>>>(x, Wd, bd, lg, lb, (float*)d_out);
}

// round 2
// speedup vs baseline: 1.0555x; 1.0555x over previous
#include <cuda_runtime.h>
#include <math.h>

#define BB 8
#define SS 200
#define HH 4
#define DD 64
#define HID 256
#define NBS (BB*SS)   // 1600
#define ITILE 4

// scratch (device globals; no allocation allowed)
__device__ float g_q[NBS*HID];
__device__ float g_kpos[NBS*HID];
__device__ float g_vpos[NBS*HID];
__device__ float g_qo[BB*HH*SS];
__device__ float g_ko[BB*HH*SS];
__device__ float g_qd[BB*HH*SS];
__device__ float g_kd[BB*HH*SS];
__device__ float g_ctx[NBS*HID];

// ---------------------------------------------------------------------------
// Kernel 1: fused QKV projection, split-K x2 (512 threads), M=8 rows/block
// ---------------------------------------------------------------------------
__global__ __launch_bounds__(512) void qkv_kernel(
    const float* __restrict__ x,
    const float* __restrict__ posK, const float* __restrict__ posV,
    const float* __restrict__ Wq, const float* __restrict__ bq,
    const float* __restrict__ Wk, const float* __restrict__ bk,
    const float* __restrict__ Wv, const float* __restrict__ bv,
    const float* __restrict__ order_w, const float* __restrict__ dist_w)
{
    const int tid  = threadIdx.x;
    const int f    = tid & 255;
    const int half = tid >> 8;
    const int r0   = blockIdx.x * 8;

    __shared__ float xs[8][HID];     // 8KB
    __shared__ float psq[8][HID];    // partial q (half1), then final q
    __shared__ float psk[8][HID];    // partial k (half1), then final k
    __shared__ float psv[8][HID];    // partial v (half1)

    for (int t = tid; t < 8 * HID; t += 512)
        xs[t >> 8][t & 255] = x[(r0 + (t >> 8)) * HID + (t & 255)];
    __syncthreads();

    float aq[8], ak[8], av[8];
    const float vbq = half ? 0.f : bq[f];
    const float vbk = half ? 0.f : bk[f];
    const float vbv = half ? 0.f : bv[f];
    #pragma unroll
    for (int m = 0; m < 8; m++) { aq[m] = vbq; ak[m] = vbk; av[m] = vbv; }

    const int g0 = half * 128;
    #pragma unroll 4
    for (int g = g0; g < g0 + 128; g++) {
        const float wq = Wq[g * HID + f];
        const float wk = Wk[g * HID + f];
        const float wv = Wv[g * HID + f];
        #pragma unroll
        for (int m = 0; m < 8; m++) {
            const float xv = xs[m][g];
            aq[m] += xv * wq;
            ak[m] += xv * wk;
            av[m] += xv * wv;
        }
    }

    if (half == 1) {
        #pragma unroll
        for (int m = 0; m < 8; m++) {
            psq[m][f] = aq[m]; psk[m][f] = ak[m]; psv[m][f] = av[m];
        }
    }
    __syncthreads();

    if (half == 0) {
        #pragma unroll
        for (int m = 0; m < 8; m++) {
            const int row = r0 + m;
            const float qv = aq[m] + psq[m][f];
            const float kv = ak[m] + psk[m][f];
            const float vv = av[m] + psv[m][f];
            g_q[row * HID + f]    = qv;
            psq[m][f]             = qv;    // final q for dots
            psk[m][f]             = kv;    // final k for dots
            g_kpos[row * HID + f] = kv + posK[row * HID + f];
            g_vpos[row * HID + f] = vv + posV[row * HID + f];
        }
    }
    __syncthreads();

    // order/dist scalar dots on first 8 warps (half 0): warp m reduces row r0+m
    if (half == 0) {
        const int w = f >> 5, l = f & 31;
        const int row = r0 + w;
        const int b = row / SS, s = row % SS;
        #pragma unroll
        for (int h = 0; h < HH; h++) {
            float qo = psq[w][h*64 + l] * order_w[l]      + psq[w][h*64 + 32 + l] * order_w[32 + l];
            float qd = psq[w][h*64 + l] * dist_w[l]       + psq[w][h*64 + 32 + l] * dist_w[32 + l];
            float ko = psk[w][h*64 + l] * order_w[64 + l] + psk[w][h*64 + 32 + l] * order_w[96 + l];
            float kd = psk[w][h*64 + l] * dist_w[64 + l]  + psk[w][h*64 + 32 + l] * dist_w[96 + l];
            #pragma unroll
            for (int off = 16; off; off >>= 1) {
                qo += __shfl_xor_sync(0xffffffffu, qo, off);
                qd += __shfl_xor_sync(0xffffffffu, qd, off);
                ko += __shfl_xor_sync(0xffffffffu, ko, off);
                kd += __shfl_xor_sync(0xffffffffu, kd, off);
            }
            if (l == 0) {
                const int idx = (b * HH + h) * SS + s;
                g_qo[idx] = qo; g_qd[idx] = qd; g_ko[idx] = ko; g_kd[idx] = kd;
            }
        }
    }
}

// ---------------------------------------------------------------------------
// Kernel 2: attention, ITILE=4 query rows per block. 256 threads.
// ---------------------------------------------------------------------------
__global__ __launch_bounds__(256) void attn_kernel(
    const float* __restrict__ timeK, const float* __restrict__ timeV,
    const float* __restrict__ mask,
    const float* __restrict__ p_order_b, const float* __restrict__ p_dist_b,
    const float* __restrict__ p_scalar)
{
    const int tid = threadIdx.x;
    const int blk = blockIdx.x;
    const int b  = blk / (SS / ITILE);
    const int i0 = (blk % (SS / ITILE)) * ITILE;
    const int w = tid >> 5, l = tid & 31;

    __shared__ float sc[ITILE][HH][SS];     // scores -> un-normalized probs
    __shared__ float q_sh[ITILE][HID];
    __shared__ float qos[ITILE][HH], qds[ITILE][HH];
    __shared__ float inv_s[ITILE][HH];
    __shared__ float dl[SS];                // log(|d|+1) table

    #pragma unroll
    for (int it = 0; it < ITILE; it++)
        q_sh[it][tid] = g_q[((size_t)(b * SS + i0 + it)) * HID + tid];
    if (tid < ITILE * HH) {
        const int it = tid >> 2, h = tid & 3;
        qos[it][h] = g_qo[(b * HH + h) * SS + i0 + it];
        qds[it][h] = g_qd[(b * HH + h) * SS + i0 + it];
    }
    if (tid < SS) dl[tid] = __logf((float)tid + 1.f);
    __syncthreads();

    // per-lane fixed q slice: floats [8l, 8l+8)
    float4 q0[ITILE], q1[ITILE];
    #pragma unroll
    for (int it = 0; it < ITILE; it++) {
        q0[it] = *(const float4*)&q_sh[it][l * 8];
        q1[it] = *(const float4*)&q_sh[it][l * 8 + 4];
    }
    const int hh = l >> 3;  // head owned by this 8-lane group

    const float* tkb[ITILE];
    #pragma unroll
    for (int it = 0; it < ITILE; it++)
        tkb[it] = timeK + ((size_t)(b * SS + i0 + it)) * SS * HID;

    // ---- phase 1: raw scores  q_i . (timeK_ij + k_j + posK_j) ----
    for (int j = w; j < SS; j += 8) {
        const float4* kp = (const float4*)(g_kpos + (size_t)(b * SS + j) * HID);
        const float4 k0 = kp[2 * l], k1 = kp[2 * l + 1];
        #pragma unroll
        for (int it = 0; it < ITILE; it++) {
            const float4* tk = (const float4*)(tkb[it] + (size_t)j * HID);
            const float4 t0 = tk[2 * l], t1 = tk[2 * l + 1];
            float p = q0[it].x * (t0.x + k0.x) + q0[it].y * (t0.y + k0.y)
                    + q0[it].z * (t0.z + k0.z) + q0[it].w * (t0.w + k0.w)
                    + q1[it].x * (t1.x + k1.x) + q1[it].y * (t1.y + k1.y)
                    + q1[it].z * (t1.z + k1.z) + q1[it].w * (t1.w + k1.w);
            p += __shfl_xor_sync(0xffffffffu, p, 1);
            p += __shfl_xor_sync(0xffffffffu, p, 2);
            p += __shfl_xor_sync(0xffffffffu, p, 4);
            if ((l & 7) == 0) sc[it][hh][j] = p;
        }
    }
    __syncthreads();

    // ---- phase 2: order/dist error terms, scale, mask ----
    const float order_b = *p_order_b;
    const float dist_b  = *p_dist_b;
    const float sc2 = p_scalar[0] * p_scalar[0] * 0.5f;
    for (int idx = tid; idx < ITILE * HH * SS; idx += 256) {
        const int it = idx / (HH * SS);
        const int rem = idx - it * (HH * SS);
        const int h = rem / SS, j = rem - (rem / SS) * SS;
        const int i = i0 + it;
        const float z = qos[it][h] + g_ko[(b * HH + h) * SS + j] + order_b;
        // log(sigmoid(z)) = -softplus(-z); log(1-sigmoid(z)) = -softplus(z)
        const float zz = (j > i) ? -z : z;
        const float eo = -(fmaxf(zz, 0.f) + __logf(1.f + __expf(-fabsf(zz))));
        const float gd = dl[abs(j - i)];
        const float pd = qds[it][h] + g_kd[(b * HH + h) * SS + j] + dist_b;
        const float ed = -(gd - pd) * (gd - pd) * sc2;
        sc[it][h][j] = (sc[it][h][j] + eo + ed) * 0.125f
                     + mask[((size_t)b * SS + i) * SS + j];
    }
    __syncthreads();

    // ---- phase 3: softmax; store exp, keep 1/sum ----
    for (int pair = w; pair < ITILE * HH; pair += 8) {
        const int it = pair >> 2, h = pair & 3;
        float m = -1e30f;
        for (int j = l; j < SS; j += 32) m = fmaxf(m, sc[it][h][j]);
        #pragma unroll
        for (int off = 16; off; off >>= 1)
            m = fmaxf(m, __shfl_xor_sync(0xffffffffu, m, off));
        float sum = 0.f;
        for (int j = l; j < SS; j += 32) {
            const float e = __expf(sc[it][h][j] - m);
            sc[it][h][j] = e;
            sum += e;
        }
        #pragma unroll
        for (int off = 16; off; off >>= 1)
            sum += __shfl_xor_sync(0xffffffffu, sum, off);
        if (l == 0) inv_s[it][h] = 1.f / sum;
    }
    __syncthreads();

    // ---- phase 4: ctx accumulate streaming timeV + vpos ----
    const int f = tid;
    const int h = f >> 6;
    const float* tvb[ITILE];
    #pragma unroll
    for (int it = 0; it < ITILE; it++)
        tvb[it] = timeV + ((size_t)(b * SS + i0 + it)) * SS * HID + f;
    const float* vp = g_vpos + (size_t)b * SS * HID + f;

    float acc[ITILE];
    #pragma unroll
    for (int it = 0; it < ITILE; it++) acc[it] = 0.f;

    #pragma unroll 2
    for (int j = 0; j < SS; j++) {
        const float vpv = vp[(size_t)j * HID];
        #pragma unroll
        for (int it = 0; it < ITILE; it++)
            acc[it] += sc[it][h][j] * (tvb[it][(size_t)j * HID] + vpv);
    }
    #pragma unroll
    for (int it = 0; it < ITILE; it++)
        g_ctx[((size_t)(b * SS + i0 + it)) * HID + f] = acc[it] * inv_s[it][h];
}

// ---------------------------------------------------------------------------
// Kernel 3: output projection split-K x2 (512 threads) + residual + LayerNorm
// ---------------------------------------------------------------------------
__global__ __launch_bounds__(512) void outln_kernel(
    const float* __restrict__ x,
    const float* __restrict__ Wd, const float* __restrict__ bd,
    const float* __restrict__ ln_g, const float* __restrict__ ln_b,
    float* __restrict__ out)
{
    const int tid  = threadIdx.x;
    const int f    = tid & 255;
    const int half = tid >> 8;
    const int r0   = blockIdx.x * 8;

    __shared__ float cs[8][HID];
    __shared__ float ps[8][HID];
    __shared__ float hsm[8][HID];
    __shared__ float mu[8], rstd[8];

    for (int t = tid; t < 8 * HID; t += 512)
        cs[t >> 8][t & 255] = g_ctx[(r0 + (t >> 8)) * HID + (t & 255)];
    __syncthreads();

    float acc[8];
    const float bdf = half ? 0.f : bd[f];
    #pragma unroll
    for (int m = 0; m < 8; m++) acc[m] = bdf;

    const int g0 = half * 128;
    #pragma unroll 4
    for (int g = g0; g < g0 + 128; g++) {
        const float wv = Wd[g * HID + f];
        #pragma unroll
        for (int m = 0; m < 8; m++) acc[m] += cs[m][g] * wv;
    }

    if (half == 1) {
        #pragma unroll
        for (int m = 0; m < 8; m++) ps[m][f] = acc[m];
    }
    __syncthreads();

    if (half == 0) {
        #pragma unroll
        for (int m = 0; m < 8; m++)
            hsm[m][f] = acc[m] + ps[m][f] + x[(r0 + m) * HID + f];
    }
    __syncthreads();

    if (half == 0) {
        const int w = f >> 5, l = f & 31;
        float s = 0.f, s2 = 0.f;
        #pragma unroll
        for (int t = 0; t < 8; t++) {
            const float v = hsm[w][l + 32 * t];
            s += v; s2 += v * v;
        }
        #pragma unroll
        for (int off = 16; off; off >>= 1) {
            s  += __shfl_xor_sync(0xffffffffu, s,  off);
            s2 += __shfl_xor_sync(0xffffffffu, s2, off);
        }
        if (l == 0) {
            const float m_  = s / HID;
            const float var = s2 / HID - m_ * m_;
            mu[w]   = m_;
            rstd[w] = rsqrtf(var + 1e-12f);
        }
    }
    __syncthreads();

    if (half == 0) {
        const float gf = ln_g[f], bf = ln_b[f];
        #pragma unroll
        for (int m = 0; m < 8; m++)
            out[(r0 + m) * HID + f] = (hsm[m][f] - mu[m]) * rstd[m] * gf + bf;
    }
}

// ---------------------------------------------------------------------------
extern "C" void kernel_launch(void* const* d_in, const int* in_sizes, int n_in,
                              void* d_out, int out_size)
{
    const float* x     = (const float*)d_in[0];
    const float* mask  = (const float*)d_in[1];
    const float* posK  = (const float*)d_in[2];
    const float* posV  = (const float*)d_in[3];
    const float* timeK = (const float*)d_in[4];
    const float* timeV = (const float*)d_in[5];
    const float* Wq = (const float*)d_in[6];  const float* bq = (const float*)d_in[7];
    const float* Wk = (const float*)d_in[8];  const float* bk = (const float*)d_in[9];
    const float* Wv = (const float*)d_in[10]; const float* bv = (const float*)d_in[11];
    const float* ow = (const float*)d_in[12]; const float* ob = (const float*)d_in[13];
    const float* dw = (const float*)d_in[14]; const float* db = (const float*)d_in[15];
    const float* sca = (const float*)d_in[16];
    const float* Wd = (const float*)d_in[17]; const float* bd = (const float*)d_in[18];
    const float* lg = (const float*)d_in[19]; const float* lb = (const float*)d_in[20];

    qkv_kernel<<<NBS / 8, 512>>>(x, posK, posV, Wq, bq, Wk, bk, Wv, bv, ow, dw);
    attn_kernel<<<NBS / ITILE, 256>>>(timeK, timeV, mask, ob, db, sca);
    outln_kernel<<<NBS / 8, 512>>>(x, Wd, bd, lg, lb, (float*)d_out);
}

// round 3
// speedup vs baseline: 1.2416x; 1.1764x over previous
#include <cuda_runtime.h>
#include <math.h>

#define BB 8
#define SS 200
#define HH 4
#define DD 64
#define HID 256
#define NBS (BB*SS)   // 1600
#define ITILE 4

// scratch (device globals; no allocation allowed)
__device__ float g_q[NBS*HID];
__device__ float g_k[NBS*HID];
__device__ float g_kpos[NBS*HID];
__device__ float g_vpos[NBS*HID];
__device__ float g_qo[BB*HH*SS];
__device__ float g_ko[BB*HH*SS];
__device__ float g_qd[BB*HH*SS];
__device__ float g_kd[BB*HH*SS];
__device__ float g_ctx[NBS*HID];

// ---------------------------------------------------------------------------
// Kernel 1: one (8-row, matrix) tile per block; split-K x4 inside the block.
// Thread (s=tid/64, c=tid%64) accumulates 8 rows x 4 cols over 64 k-values.
// ---------------------------------------------------------------------------
__global__ __launch_bounds__(256) void gemm3_kernel(
    const float* __restrict__ x,
    const float* __restrict__ Wq, const float* __restrict__ bq,
    const float* __restrict__ Wk, const float* __restrict__ bk,
    const float* __restrict__ Wv, const float* __restrict__ bv,
    const float* __restrict__ posV)
{
    const int r0  = blockIdx.x * 8;
    const int mat = blockIdx.y;
    const float* __restrict__ W    = (mat == 0) ? Wq : (mat == 1) ? Wk : Wv;
    const float* __restrict__ bias = (mat == 0) ? bq : (mat == 1) ? bk : bv;

    const int tid = threadIdx.x;
    const int s   = tid >> 6;   // k-slice 0..3
    const int c   = tid & 63;   // col group: cols [4c, 4c+4)

    __shared__ float xs[HID][8];        // x transposed: xs[g][m]  (8KB)
    __shared__ float red[3][8][HID];    // partials from slices 1..3 (24KB)

    for (int t = tid; t < 8 * HID; t += 256) {
        const int m = t >> 8, g = t & 255;
        xs[g][m] = x[(r0 + m) * HID + g];
    }
    __syncthreads();

    float4 acc[8];
    if (s == 0) {
        const float4 b4 = *(const float4*)&bias[4 * c];
        #pragma unroll
        for (int m = 0; m < 8; m++) acc[m] = b4;
    } else {
        #pragma unroll
        for (int m = 0; m < 8; m++) acc[m] = make_float4(0.f, 0.f, 0.f, 0.f);
    }

    const float* __restrict__ Wp = W + (size_t)(s * 64) * HID + 4 * c;
    const float* __restrict__ xp = &xs[s * 64][0];
    #pragma unroll 4
    for (int gi = 0; gi < 64; gi++) {
        const float4 w = *(const float4*)(Wp + (size_t)gi * HID);
        #pragma unroll
        for (int m = 0; m < 8; m++) {
            const float xv = xp[gi * 8 + m];
            acc[m].x += xv * w.x; acc[m].y += xv * w.y;
            acc[m].z += xv * w.z; acc[m].w += xv * w.w;
        }
    }

    if (s > 0) {
        #pragma unroll
        for (int m = 0; m < 8; m++)
            *(float4*)&red[s - 1][m][4 * c] = acc[m];
    }
    __syncthreads();

    if (s == 0) {
        #pragma unroll
        for (int m = 0; m < 8; m++) {
            const float4 r0v = *(const float4*)&red[0][m][4 * c];
            const float4 r1v = *(const float4*)&red[1][m][4 * c];
            const float4 r2v = *(const float4*)&red[2][m][4 * c];
            float4 a = acc[m];
            a.x += r0v.x + r1v.x + r2v.x;
            a.y += r0v.y + r1v.y + r2v.y;
            a.z += r0v.z + r1v.z + r2v.z;
            a.w += r0v.w + r1v.w + r2v.w;
            const int row = r0 + m;
            if (mat == 0) {
                *(float4*)&g_q[(size_t)row * HID + 4 * c] = a;
            } else if (mat == 1) {
                *(float4*)&g_k[(size_t)row * HID + 4 * c] = a;
            } else {
                const float4 pv = *(const float4*)&posV[(size_t)row * HID + 4 * c];
                a.x += pv.x; a.y += pv.y; a.z += pv.z; a.w += pv.w;
                *(float4*)&g_vpos[(size_t)row * HID + 4 * c] = a;
            }
        }
    }
}

// ---------------------------------------------------------------------------
// Kernel 1b: kpos = k + posK; order/dist scalar dot tables. 8 rows/block.
// ---------------------------------------------------------------------------
__global__ __launch_bounds__(256) void post_kernel(
    const float* __restrict__ posK,
    const float* __restrict__ order_w, const float* __restrict__ dist_w)
{
    const int f  = threadIdx.x;
    const int r0 = blockIdx.x * 8;

    __shared__ float qs[8][HID];
    __shared__ float ks[8][HID];

    #pragma unroll
    for (int m = 0; m < 8; m++) {
        const int row = r0 + m;
        const float kv = g_k[(size_t)row * HID + f];
        qs[m][f] = g_q[(size_t)row * HID + f];
        ks[m][f] = kv;
        g_kpos[(size_t)row * HID + f] = kv + posK[(size_t)row * HID + f];
    }
    __syncthreads();

    const int w = f >> 5, l = f & 31;
    const int row = r0 + w;
    const int b = row / SS, sidx = row % SS;
    #pragma unroll
    for (int h = 0; h < HH; h++) {
        float qo = qs[w][h*64 + l] * order_w[l]      + qs[w][h*64 + 32 + l] * order_w[32 + l];
        float qd = qs[w][h*64 + l] * dist_w[l]       + qs[w][h*64 + 32 + l] * dist_w[32 + l];
        float ko = ks[w][h*64 + l] * order_w[64 + l] + ks[w][h*64 + 32 + l] * order_w[96 + l];
        float kd = ks[w][h*64 + l] * dist_w[64 + l]  + ks[w][h*64 + 32 + l] * dist_w[96 + l];
        #pragma unroll
        for (int off = 16; off; off >>= 1) {
            qo += __shfl_xor_sync(0xffffffffu, qo, off);
            qd += __shfl_xor_sync(0xffffffffu, qd, off);
            ko += __shfl_xor_sync(0xffffffffu, ko, off);
            kd += __shfl_xor_sync(0xffffffffu, kd, off);
        }
        if (l == 0) {
            const int idx = (b * HH + h) * SS + sidx;
            g_qo[idx] = qo; g_qd[idx] = qd; g_ko[idx] = ko; g_kd[idx] = kd;
        }
    }
}

// ---------------------------------------------------------------------------
// Kernel 2: attention, ITILE=4 query rows per block. 256 threads.
// ---------------------------------------------------------------------------
__global__ __launch_bounds__(256) void attn_kernel(
    const float* __restrict__ timeK, const float* __restrict__ timeV,
    const float* __restrict__ mask,
    const float* __restrict__ p_order_b, const float* __restrict__ p_dist_b,
    const float* __restrict__ p_scalar)
{
    const int tid = threadIdx.x;
    const int blk = blockIdx.x;
    const int b  = blk / (SS / ITILE);
    const int i0 = (blk % (SS / ITILE)) * ITILE;
    const int w = tid >> 5, l = tid & 31;

    __shared__ float sc[ITILE][HH][SS];     // scores -> un-normalized probs
    __shared__ float q_sh[ITILE][HID];
    __shared__ float qos[ITILE][HH], qds[ITILE][HH];
    __shared__ float inv_s[ITILE][HH];
    __shared__ float dl[SS];                // log(|d|+1) table

    #pragma unroll
    for (int it = 0; it < ITILE; it++)
        q_sh[it][tid] = g_q[((size_t)(b * SS + i0 + it)) * HID + tid];
    if (tid < ITILE * HH) {
        const int it = tid >> 2, h = tid & 3;
        qos[it][h] = g_qo[(b * HH + h) * SS + i0 + it];
        qds[it][h] = g_qd[(b * HH + h) * SS + i0 + it];
    }
    if (tid < SS) dl[tid] = __logf((float)tid + 1.f);
    __syncthreads();

    float4 q0[ITILE], q1[ITILE];
    #pragma unroll
    for (int it = 0; it < ITILE; it++) {
        q0[it] = *(const float4*)&q_sh[it][l * 8];
        q1[it] = *(const float4*)&q_sh[it][l * 8 + 4];
    }
    const int hh = l >> 3;

    const float* tkb[ITILE];
    #pragma unroll
    for (int it = 0; it < ITILE; it++)
        tkb[it] = timeK + ((size_t)(b * SS + i0 + it)) * SS * HID;

    // ---- phase 1: raw scores ----
    for (int j = w; j < SS; j += 8) {
        const float4* kp = (const float4*)(g_kpos + (size_t)(b * SS + j) * HID);
        const float4 k0 = kp[2 * l], k1 = kp[2 * l + 1];
        #pragma unroll
        for (int it = 0; it < ITILE; it++) {
            const float4* tk = (const float4*)(tkb[it] + (size_t)j * HID);
            const float4 t0 = tk[2 * l], t1 = tk[2 * l + 1];
            float p = q0[it].x * (t0.x + k0.x) + q0[it].y * (t0.y + k0.y)
                    + q0[it].z * (t0.z + k0.z) + q0[it].w * (t0.w + k0.w)
                    + q1[it].x * (t1.x + k1.x) + q1[it].y * (t1.y + k1.y)
                    + q1[it].z * (t1.z + k1.z) + q1[it].w * (t1.w + k1.w);
            p += __shfl_xor_sync(0xffffffffu, p, 1);
            p += __shfl_xor_sync(0xffffffffu, p, 2);
            p += __shfl_xor_sync(0xffffffffu, p, 4);
            if ((l & 7) == 0) sc[it][hh][j] = p;
        }
    }
    __syncthreads();

    // ---- phase 2: order/dist error terms, scale, mask ----
    const float order_b = *p_order_b;
    const float dist_b  = *p_dist_b;
    const float sc2 = p_scalar[0] * p_scalar[0] * 0.5f;
    for (int idx = tid; idx < ITILE * HH * SS; idx += 256) {
        const int it = idx / (HH * SS);
        const int rem = idx - it * (HH * SS);
        const int h = rem / SS, j = rem - (rem / SS) * SS;
        const int i = i0 + it;
        const float z = qos[it][h] + g_ko[(b * HH + h) * SS + j] + order_b;
        const float zz = (j > i) ? -z : z;
        const float eo = -(fmaxf(zz, 0.f) + __logf(1.f + __expf(-fabsf(zz))));
        const float gd = dl[abs(j - i)];
        const float pd = qds[it][h] + g_kd[(b * HH + h) * SS + j] + dist_b;
        const float ed = -(gd - pd) * (gd - pd) * sc2;
        sc[it][h][j] = (sc[it][h][j] + eo + ed) * 0.125f
                     + mask[((size_t)b * SS + i) * SS + j];
    }
    __syncthreads();

    // ---- phase 3: softmax ----
    for (int pair = w; pair < ITILE * HH; pair += 8) {
        const int it = pair >> 2, h = pair & 3;
        float m = -1e30f;
        for (int j = l; j < SS; j += 32) m = fmaxf(m, sc[it][h][j]);
        #pragma unroll
        for (int off = 16; off; off >>= 1)
            m = fmaxf(m, __shfl_xor_sync(0xffffffffu, m, off));
        float sum = 0.f;
        for (int j = l; j < SS; j += 32) {
            const float e = __expf(sc[it][h][j] - m);
            sc[it][h][j] = e;
            sum += e;
        }
        #pragma unroll
        for (int off = 16; off; off >>= 1)
            sum += __shfl_xor_sync(0xffffffffu, sum, off);
        if (l == 0) inv_s[it][h] = 1.f / sum;
    }
    __syncthreads();

    // ---- phase 4: ctx ----
    const int f = tid;
    const int h = f >> 6;
    const float* tvb[ITILE];
    #pragma unroll
    for (int it = 0; it < ITILE; it++)
        tvb[it] = timeV + ((size_t)(b * SS + i0 + it)) * SS * HID + f;
    const float* vp = g_vpos + (size_t)b * SS * HID + f;

    float acc[ITILE];
    #pragma unroll
    for (int it = 0; it < ITILE; it++) acc[it] = 0.f;

    #pragma unroll 2
    for (int j = 0; j < SS; j++) {
        const float vpv = vp[(size_t)j * HID];
        #pragma unroll
        for (int it = 0; it < ITILE; it++)
            acc[it] += sc[it][h][j] * (tvb[it][(size_t)j * HID] + vpv);
    }
    #pragma unroll
    for (int it = 0; it < ITILE; it++)
        g_ctx[((size_t)(b * SS + i0 + it)) * HID + f] = acc[it] * inv_s[it][h];
}

// ---------------------------------------------------------------------------
// Kernel 3: output projection (split-K x4, 8 rows x 4 cols) + residual + LN
// ---------------------------------------------------------------------------
__global__ __launch_bounds__(256) void outln_kernel(
    const float* __restrict__ x,
    const float* __restrict__ Wd, const float* __restrict__ bd,
    const float* __restrict__ ln_g, const float* __restrict__ ln_b,
    float* __restrict__ out)
{
    const int r0  = blockIdx.x * 8;
    const int tid = threadIdx.x;
    const int s   = tid >> 6;
    const int c   = tid & 63;

    __shared__ float cs[HID][8];        // ctx transposed
    __shared__ float red[3][8][HID];
    __shared__ float hsm[8][HID];
    __shared__ float mu[8], rstd[8];

    for (int t = tid; t < 8 * HID; t += 256) {
        const int m = t >> 8, g = t & 255;
        cs[g][m] = g_ctx[(size_t)(r0 + m) * HID + g];
    }
    __syncthreads();

    float4 acc[8];
    if (s == 0) {
        const float4 b4 = *(const float4*)&bd[4 * c];
        #pragma unroll
        for (int m = 0; m < 8; m++) acc[m] = b4;
    } else {
        #pragma unroll
        for (int m = 0; m < 8; m++) acc[m] = make_float4(0.f, 0.f, 0.f, 0.f);
    }

    const float* __restrict__ Wp = Wd + (size_t)(s * 64) * HID + 4 * c;
    const float* __restrict__ xp = &cs[s * 64][0];
    #pragma unroll 4
    for (int gi = 0; gi < 64; gi++) {
        const float4 w = *(const float4*)(Wp + (size_t)gi * HID);
        #pragma unroll
        for (int m = 0; m < 8; m++) {
            const float xv = xp[gi * 8 + m];
            acc[m].x += xv * w.x; acc[m].y += xv * w.y;
            acc[m].z += xv * w.z; acc[m].w += xv * w.w;
        }
    }

    if (s > 0) {
        #pragma unroll
        for (int m = 0; m < 8; m++)
            *(float4*)&red[s - 1][m][4 * c] = acc[m];
    }
    __syncthreads();

    if (s == 0) {
        #pragma unroll
        for (int m = 0; m < 8; m++) {
            const float4 r0v = *(const float4*)&red[0][m][4 * c];
            const float4 r1v = *(const float4*)&red[1][m][4 * c];
            const float4 r2v = *(const float4*)&red[2][m][4 * c];
            const float4 xv  = *(const float4*)&x[(size_t)(r0 + m) * HID + 4 * c];
            float4 a = acc[m];
            a.x += r0v.x + r1v.x + r2v.x + xv.x;
            a.y += r0v.y + r1v.y + r2v.y + xv.y;
            a.z += r0v.z + r1v.z + r2v.z + xv.z;
            a.w += r0v.w + r1v.w + r2v.w + xv.w;
            *(float4*)&hsm[m][4 * c] = a;
        }
    }
    __syncthreads();

    const int w = tid >> 5, l = tid & 31;
    float sum = 0.f, sum2 = 0.f;
    #pragma unroll
    for (int t = 0; t < 8; t++) {
        const float v = hsm[w][l + 32 * t];
        sum += v; sum2 += v * v;
    }
    #pragma unroll
    for (int off = 16; off; off >>= 1) {
        sum  += __shfl_xor_sync(0xffffffffu, sum,  off);
        sum2 += __shfl_xor_sync(0xffffffffu, sum2, off);
    }
    if (l == 0) {
        const float m_  = sum / HID;
        const float var = sum2 / HID - m_ * m_;
        mu[w]   = m_;
        rstd[w] = rsqrtf(var + 1e-12f);
    }
    __syncthreads();

    const int f = tid;
    const float gf = ln_g[f], bf = ln_b[f];
    #pragma unroll
    for (int m = 0; m < 8; m++)
        out[(size_t)(r0 + m) * HID + f] = (hsm[m][f] - mu[m]) * rstd[m] * gf + bf;
}

// ---------------------------------------------------------------------------
extern "C" void kernel_launch(void* const* d_in, const int* in_sizes, int n_in,
                              void* d_out, int out_size)
{
    const float* x     = (const float*)d_in[0];
    const float* mask  = (const float*)d_in[1];
    const float* posK  = (const float*)d_in[2];
    const float* posV  = (const float*)d_in[3];
    const float* timeK = (const float*)d_in[4];
    const float* timeV = (const float*)d_in[5];
    const float* Wq = (const float*)d_in[6];  const float* bq = (const float*)d_in[7];
    const float* Wk = (const float*)d_in[8];  const float* bk = (const float*)d_in[9];
    const float* Wv = (const float*)d_in[10]; const float* bv = (const float*)d_in[11];
    const float* ow = (const float*)d_in[12]; const float* ob = (const float*)d_in[13];
    const float* dw = (const float*)d_in[14]; const float* db = (const float*)d_in[15];
    const float* sca = (const float*)d_in[16];
    const float* Wd = (const float*)d_in[17]; const float* bd = (const float*)d_in[18];
    const float* lg = (const float*)d_in[19]; const float* lb = (const float*)d_in[20];

    dim3 g1(NBS / 8, 3);
    gemm3_kernel<<<g1, 256>>>(x, Wq, bq, Wk, bk, Wv, bv, posV);
    post_kernel<<<NBS / 8, 256>>>(posK, ow, dw);
    attn_kernel<<<NBS / ITILE, 256>>>(timeK, timeV, mask, ob, db, sca);
    outln_kernel<<<NBS / 8, 256>>>(x, Wd, bd, lg, lb, (float*)d_out);
}